// round 9
// baseline (speedup 1.0000x reference)
#include <cuda_runtime.h>
#include <cstdint>

#define NUM_NODES 500000
#define D 128
#define U 32
#define T 4
#define A 32
#define N_SRC 65536
#define B 8192
#define E 262144
#define BB 16
#define NBINS (T * B)   // 32768
#define CAP 96          // slot capacity per bin (max observed ~58)

typedef unsigned long long ull;

#define FMA_F32X2(d, a, b, c) \
    asm("fma.rn.f32x2 %0, %1, %2, %3;" : "=l"(d) : "l"(a), "l"(b), "l"(c))
#define PACK_DUP_F32X2(d, s) \
    asm("mov.b64 %0, {%1, %1};" : "=l"(d) : "f"(s))

// Scratch
__device__ float g_agg[B * T * U];        // 4 MB
__device__ int   g_cnt[NBINS];            // 128 KB
__device__ int   g_slots[NBINS * CAP];    // 12 MB: row-ids per bin

// ---------------------------------------------------------------------------
// K1: scatter edges into capacity bins. 8 edges/thread, int4 index loads,
// 8 independent atomic chains. Overflow (pos>=CAP) red-adds directly.
// ---------------------------------------------------------------------------
__global__ __launch_bounds__(256) void scatter_kernel(
    const float* __restrict__ nte_tab,
    const int* __restrict__ input_nodes,
    const int* __restrict__ edge_src,
    const int* __restrict__ edge_dst) {
    const int g = (blockIdx.x * 256 + threadIdx.x) * 8;   // flat edge index, 8 per thread
    const int t = g >> 18;                                // E = 2^18

    const int4 s0 = __ldg((const int4*)&edge_src[g]);
    const int4 s1 = __ldg((const int4*)&edge_src[g + 4]);
    const int4 d0 = __ldg((const int4*)&edge_dst[g]);
    const int4 d1 = __ldg((const int4*)&edge_dst[g + 4]);

    int src[8] = {s0.x, s0.y, s0.z, s0.w, s1.x, s1.y, s1.z, s1.w};
    int dst[8] = {d0.x, d0.y, d0.z, d0.w, d1.x, d1.y, d1.z, d1.w};

    int row[8];
    #pragma unroll
    for (int j = 0; j < 8; j++) row[j] = __ldg(&input_nodes[src[j]]) * T + t;

    int pos[8], bin[8];
    #pragma unroll
    for (int j = 0; j < 8; j++) {
        bin[j] = t * B + dst[j];
        pos[j] = atomicAdd(&g_cnt[bin[j]], 1);
    }
    #pragma unroll
    for (int j = 0; j < 8; j++) {
        if (pos[j] < CAP) {
            g_slots[bin[j] * CAP + pos[j]] = row[j];
        } else {
            // statistically-never fallback: red row into g_agg directly
            const float4* r = (const float4*)nte_tab + (size_t)row[j] * (U / 4);
            float* p = g_agg + ((size_t)dst[j] * T + t) * U;
            #pragma unroll
            for (int q = 0; q < U / 4; q++) {
                float4 v = __ldg(&r[q]);
                asm volatile("red.global.add.v4.f32 [%0], {%1,%2,%3,%4};"
                             :: "l"(p + q * 4), "f"(v.x), "f"(v.y), "f"(v.z), "f"(v.w)
                             : "memory");
            }
        }
    }
}

// ---------------------------------------------------------------------------
// K2: pull aggregation. One warp per (t,dst) bin; 4 edges in flight,
// 8 lanes x float4 per edge (one 128B line per group). Plain store result
// (+ g_agg fallback contents).
// ---------------------------------------------------------------------------
__global__ __launch_bounds__(256) void pull_kernel(const float* __restrict__ nte_tab) {
    const int bin  = blockIdx.x * 8 + (threadIdx.x >> 5);
    const int lane = threadIdx.x & 31;
    const int t    = bin >> 13;              // B = 2^13
    const int dstb = bin & (B - 1);

    const int cnt  = __ldg(&g_cnt[bin]);
    const int n    = cnt < CAP ? cnt : CAP;
    const int base = bin * CAP;
    const int grp  = lane >> 3;
    const int sub  = lane & 7;

    float4 acc = make_float4(0.f, 0.f, 0.f, 0.f);
    int e = grp;
    // 2 rows in flight per group (8 per warp)
    for (; e + 4 < n; e += 8) {
        const int r0 = __ldg(&g_slots[base + e]);
        const int r1 = __ldg(&g_slots[base + e + 4]);
        const float4 v0 = __ldg((const float4*)nte_tab + (size_t)r0 * (U / 4) + sub);
        const float4 v1 = __ldg((const float4*)nte_tab + (size_t)r1 * (U / 4) + sub);
        acc.x += v0.x + v1.x; acc.y += v0.y + v1.y;
        acc.z += v0.z + v1.z; acc.w += v0.w + v1.w;
    }
    for (; e < n; e += 4) {
        const int r0 = __ldg(&g_slots[base + e]);
        const float4 v0 = __ldg((const float4*)nte_tab + (size_t)r0 * (U / 4) + sub);
        acc.x += v0.x; acc.y += v0.y; acc.z += v0.z; acc.w += v0.w;
    }

    #pragma unroll
    for (int o = 8; o <= 16; o <<= 1) {
        acc.x += __shfl_xor_sync(0xFFFFFFFFu, acc.x, o);
        acc.y += __shfl_xor_sync(0xFFFFFFFFu, acc.y, o);
        acc.z += __shfl_xor_sync(0xFFFFFFFFu, acc.z, o);
        acc.w += __shfl_xor_sync(0xFFFFFFFFu, acc.w, o);
    }
    if (lane < 8) {
        float4* p = (float4*)g_agg + ((size_t)dstb * T + t) * (U / 4) + lane;
        const float4 prev = *p;   // fallback reds (usually zero)
        acc.x += prev.x; acc.y += prev.y; acc.z += prev.z; acc.w += prev.w;
        *p = acc;
    }
}

// ---------------------------------------------------------------------------
// K3: finalize (R7 version, 22.8us): attention + softmax + combine + GEMM
// + residual + normalize. BB=16 rows/block, f32x2 FMAs.
// ---------------------------------------------------------------------------
__global__ __launch_bounds__(256, 4) void finalize_kernel(
    const float* __restrict__ node_emb,
    const float* __restrict__ w,
    const float* __restrict__ ws1,
    const float* __restrict__ ws2,
    const int*  __restrict__ out_nodes,
    float*      __restrict__ out)
{
    __shared__ float nte_s[BB][T * U];
    __shared__ float scores_s[BB][T];
    __shared__ float att_s[BB][T];
    __shared__ float comb_s[BB][U];

    const int b0   = blockIdx.x * BB;
    const int tid  = threadIdx.x;
    const int lane = tid & 31;
    const int warp = tid >> 5;
    const int t    = warp & 3;
    const int bbase = (warp >> 2) * 8;

    {
        const float4* s4 = (const float4*)(g_agg + (size_t)b0 * T * U);
        float4* d4 = (float4*)&nte_s[0][0];
        #pragma unroll
        for (int i = tid; i < BB * T * U / 4; i += 256) d4[i] = s4[i];
    }
    __syncthreads();

    {
        float w1r[U];
        #pragma unroll
        for (int u = 0; u < U; u++) w1r[u] = __ldg(&ws1[(t * U + u) * A + lane]);
        const float w2r = __ldg(&ws2[t * A + lane]);

        #pragma unroll
        for (int i = 0; i < 8; i++) {
            const int bb = bbase + i;
            float acc = 0.f;
            #pragma unroll
            for (int u = 0; u < U; u++) acc += nte_s[bb][t * U + u] * w1r[u];
            float sc = tanhf(acc) * w2r;
            #pragma unroll
            for (int o = 16; o; o >>= 1) sc += __shfl_xor_sync(0xFFFFFFFFu, sc, o);
            if (lane == 0) scores_s[bb][t] = sc;
        }
    }
    __syncthreads();

    if (tid < BB) {
        float s0 = scores_s[tid][0], s1 = scores_s[tid][1];
        float s2 = scores_s[tid][2], s3 = scores_s[tid][3];
        float m = fmaxf(fmaxf(s0, s1), fmaxf(s2, s3));
        float e0 = __expf(s0 - m), e1 = __expf(s1 - m);
        float e2 = __expf(s2 - m), e3 = __expf(s3 - m);
        float inv = 1.f / (e0 + e1 + e2 + e3);
        att_s[tid][0] = e0 * inv; att_s[tid][1] = e1 * inv;
        att_s[tid][2] = e2 * inv; att_s[tid][3] = e3 * inv;
    }
    __syncthreads();

    #pragma unroll
    for (int i = tid; i < BB * U; i += 256) {
        const int bb = i >> 5, u = i & 31;
        float c = 0.f;
        #pragma unroll
        for (int tt = 0; tt < T; tt++) c += att_s[bb][tt] * nte_s[bb][tt * U + u];
        comb_s[bb][u] = c;
    }
    __syncthreads();

    ull acc[8][2];
    #pragma unroll
    for (int i = 0; i < 8; i++) { acc[i][0] = 0; acc[i][1] = 0; }

    const float4* wbase = (const float4*)w + (size_t)t * U * (D / 4) + lane;
    #pragma unroll
    for (int uc = 0; uc < U; uc += 4) {
        ull wlo[4], whi[4];
        #pragma unroll
        for (int j = 0; j < 4; j++) {
            float4 wv = __ldg(&wbase[(uc + j) * (D / 4)]);
            asm("mov.b64 %0, {%1, %2};" : "=l"(wlo[j]) : "f"(wv.x), "f"(wv.y));
            asm("mov.b64 %0, {%1, %2};" : "=l"(whi[j]) : "f"(wv.z), "f"(wv.w));
        }
        #pragma unroll
        for (int i = 0; i < 8; i++) {
            const int bb = bbase + i;
            const float4 cb = ((const float4*)&comb_s[bb][0])[uc >> 2];
            ull c2;
            PACK_DUP_F32X2(c2, cb.x);
            FMA_F32X2(acc[i][0], c2, wlo[0], acc[i][0]);
            FMA_F32X2(acc[i][1], c2, whi[0], acc[i][1]);
            PACK_DUP_F32X2(c2, cb.y);
            FMA_F32X2(acc[i][0], c2, wlo[1], acc[i][0]);
            FMA_F32X2(acc[i][1], c2, whi[1], acc[i][1]);
            PACK_DUP_F32X2(c2, cb.z);
            FMA_F32X2(acc[i][0], c2, wlo[2], acc[i][0]);
            FMA_F32X2(acc[i][1], c2, whi[2], acc[i][1]);
            PACK_DUP_F32X2(c2, cb.w);
            FMA_F32X2(acc[i][0], c2, wlo[3], acc[i][0]);
            FMA_F32X2(acc[i][1], c2, whi[3], acc[i][1]);
        }
    }

    #pragma unroll
    for (int i = 0; i < 8; i++) {
        const int bb = bbase + i;
        const int b  = b0 + bb;

        float4 o;
        asm("mov.b64 {%0, %1}, %2;" : "=f"(o.x), "=f"(o.y) : "l"(acc[i][0]));
        asm("mov.b64 {%0, %1}, %2;" : "=f"(o.z), "=f"(o.w) : "l"(acc[i][1]));

        const int nidx = __ldg(&out_nodes[b]);
        const float4 nv = __ldg((const float4*)node_emb + (size_t)nidx * (D / 4) + lane);
        o.x += nv.x; o.y += nv.y; o.z += nv.z; o.w += nv.w;

        float ss = o.x * o.x + o.y * o.y + o.z * o.z + o.w * o.w;
        #pragma unroll
        for (int off = 16; off; off >>= 1) ss += __shfl_xor_sync(0xFFFFFFFFu, ss, off);

        const float scale = 1.f / fmaxf(sqrtf(ss), 1e-12f);
        o.x *= scale; o.y *= scale; o.z *= scale; o.w *= scale;

        ((float4*)out)[(size_t)(b * T + t) * (D / 4) + lane] = o;
    }
}

// ---------------------------------------------------------------------------
// Launch
// ---------------------------------------------------------------------------
extern "C" void kernel_launch(void* const* d_in, const int* in_sizes, int n_in,
                              void* d_out, int out_size) {
    const float* node_emb     = (const float*)d_in[0];
    const float* nte_tab      = (const float*)d_in[1];
    const float* trans_w      = (const float*)d_in[2];
    const float* trans_w_s1   = (const float*)d_in[3];
    const float* trans_w_s2   = (const float*)d_in[4];
    const int*   input_nodes  = (const int*)d_in[5];
    const int*   output_nodes = (const int*)d_in[6];
    const int*   edge_src     = (const int*)d_in[7];
    const int*   edge_dst     = (const int*)d_in[8];
    float*       out          = (float*)d_out;

    void* agg_ptr = nullptr;
    cudaGetSymbolAddress(&agg_ptr, g_agg);
    cudaMemsetAsync(agg_ptr, 0, (size_t)B * T * U * sizeof(float));

    void* cnt_ptr = nullptr;
    cudaGetSymbolAddress(&cnt_ptr, g_cnt);
    cudaMemsetAsync(cnt_ptr, 0, (size_t)NBINS * sizeof(int));

    scatter_kernel<<<(T * E / 8) / 256, 256>>>(nte_tab, input_nodes, edge_src, edge_dst);

    pull_kernel<<<NBINS / 8, 256>>>(nte_tab);

    finalize_kernel<<<B / BB, 256>>>(node_emb, trans_w, trans_w_s1, trans_w_s2,
                                     output_nodes, out);
}